// round 4
// baseline (speedup 1.0000x reference)
#include <cuda_runtime.h>
#include <math_constants.h>

// Chamfer 1D via bucketed NN search, 2 launches. N = M = 16384 fp32.
// out = 0.5 * (sum_i min_j |x_i-y_j| + sum_j min_i |y_j-x_i|) / N

#define CN    16384
#define NB    4096
#define TPB   256
#define BLO   (-8.0f)
#define BRANGE 16.0f
#define BW    (BRANGE / (float)NB)
#define BINVW ((float)NB / BRANGE)

__device__ unsigned g_off[2][NB + 1];
__device__ float    g_sorted[2][CN];

__device__ __forceinline__ int bucket_of(float v) {
    int b = (int)((v - BLO) * BINVW);
    return min(NB - 1, max(0, b));
}

// ---------------------------------------------------------------------------
// K1: single block, 1024 threads. Histogram (smem atomics) -> exclusive scan
// (smem) -> counting-sort scatter (smem cursors, global writes). Also zeroes
// the output accumulator.
// ---------------------------------------------------------------------------
__global__ void __launch_bounds__(1024, 1)
build_kernel(const float* __restrict__ x, const float* __restrict__ y,
             float* __restrict__ out) {
    __shared__ unsigned sh[2][NB];   // histogram -> offsets -> cursors
    __shared__ unsigned ss[1024];    // scan workspace

    const int t = threadIdx.x;
    if (t == 0) out[0] = 0.0f;

    // Zero histograms
    #pragma unroll
    for (int k = t; k < NB; k += 1024) { sh[0][k] = 0u; sh[1][k] = 0u; }
    __syncthreads();

    // Histogram both arrays (float4 loads, smem atomics)
    const float4* x4 = reinterpret_cast<const float4*>(x);
    const float4* y4 = reinterpret_cast<const float4*>(y);
    #pragma unroll
    for (int k = t; k < CN / 4; k += 1024) {
        float4 v = x4[k];
        atomicAdd(&sh[0][bucket_of(v.x)], 1u);
        atomicAdd(&sh[0][bucket_of(v.y)], 1u);
        atomicAdd(&sh[0][bucket_of(v.z)], 1u);
        atomicAdd(&sh[0][bucket_of(v.w)], 1u);
        float4 u = y4[k];
        atomicAdd(&sh[1][bucket_of(u.x)], 1u);
        atomicAdd(&sh[1][bucket_of(u.y)], 1u);
        atomicAdd(&sh[1][bucket_of(u.z)], 1u);
        atomicAdd(&sh[1][bucket_of(u.w)], 1u);
    }
    __syncthreads();

    // Exclusive scan of both histograms; write offsets to global, convert
    // smem copy into scatter cursors.
    #pragma unroll
    for (int a = 0; a < 2; a++) {
        unsigned v0 = sh[a][4 * t + 0];
        unsigned v1 = sh[a][4 * t + 1];
        unsigned v2 = sh[a][4 * t + 2];
        unsigned v3 = sh[a][4 * t + 3];
        unsigned sum = v0 + v1 + v2 + v3;
        ss[t] = sum;
        __syncthreads();
        for (int d = 1; d < 1024; d <<= 1) {
            unsigned add = (t >= d) ? ss[t - d] : 0u;
            __syncthreads();
            ss[t] += add;
            __syncthreads();
        }
        unsigned base = ss[t] - sum;          // exclusive prefix
        unsigned o0 = base;
        unsigned o1 = o0 + v0;
        unsigned o2 = o1 + v1;
        unsigned o3 = o2 + v2;
        sh[a][4 * t + 0] = o0;  g_off[a][4 * t + 0] = o0;
        sh[a][4 * t + 1] = o1;  g_off[a][4 * t + 1] = o1;
        sh[a][4 * t + 2] = o2;  g_off[a][4 * t + 2] = o2;
        sh[a][4 * t + 3] = o3;  g_off[a][4 * t + 3] = o3;
        if (t == 1023) g_off[a][NB] = CN;
        __syncthreads();
    }

    // Counting-sort scatter (within-bucket order irrelevant -> replay-safe)
    #pragma unroll
    for (int k = t; k < CN / 4; k += 1024) {
        float4 v = x4[k];
        g_sorted[0][atomicAdd(&sh[0][bucket_of(v.x)], 1u)] = v.x;
        g_sorted[0][atomicAdd(&sh[0][bucket_of(v.y)], 1u)] = v.y;
        g_sorted[0][atomicAdd(&sh[0][bucket_of(v.z)], 1u)] = v.z;
        g_sorted[0][atomicAdd(&sh[0][bucket_of(v.w)], 1u)] = v.w;
        float4 u = y4[k];
        g_sorted[1][atomicAdd(&sh[1][bucket_of(u.x)], 1u)] = u.x;
        g_sorted[1][atomicAdd(&sh[1][bucket_of(u.y)], 1u)] = u.y;
        g_sorted[1][atomicAdd(&sh[1][bucket_of(u.z)], 1u)] = u.z;
        g_sorted[1][atomicAdd(&sh[1][bucket_of(u.w)], 1u)] = u.w;
    }
}

// ---------------------------------------------------------------------------
// K2: per-query outward ring search over the other array's buckets.
// Queries read coalesced from the ORIGINAL arrays (locality is moot: the whole
// working set is L2-resident). Pruning bound: all elements binned in bucket b
// lie at distance >= gap-to-bucket-edge (clamped outliers lie beyond the edge
// bucket, so the bound still holds).
// ---------------------------------------------------------------------------
__global__ void __launch_bounds__(TPB)
search_kernel(const float* __restrict__ x, const float* __restrict__ y,
              float* __restrict__ out) {
    const int gi = blockIdx.x * TPB + threadIdx.x;  // 0 .. 2*CN-1
    const int dir = gi >= CN;         // 0: queries=x, cands=sorted y
    const int i = gi - dir * CN;

    const float q = dir ? y[i] : x[i];
    const float* __restrict__ cArr = g_sorted[1 - dir];
    const unsigned* __restrict__ off = g_off[1 - dir];

    const int b = bucket_of(q);

    float best = CUDART_INF_F;
    for (unsigned k = off[b]; k < off[b + 1]; k++)
        best = fminf(best, fabsf(q - cArr[k]));

    int bl = b - 1, br = b + 1;
    bool goL = (bl >= 0), goR = (br < NB);
    while (goL || goR) {
        if (goL) {
            float gap = q - (BLO + (float)(bl + 1) * BW);
            if (gap >= best) {
                goL = false;
            } else {
                for (unsigned k = off[bl]; k < off[bl + 1]; k++)
                    best = fminf(best, fabsf(q - cArr[k]));
                if (--bl < 0) goL = false;
            }
        }
        if (goR) {
            float gap = (BLO + (float)br * BW) - q;
            if (gap >= best) {
                goR = false;
            } else {
                for (unsigned k = off[br]; k < off[br + 1]; k++)
                    best = fminf(best, fabsf(q - cArr[k]));
                if (++br >= NB) goR = false;
            }
        }
    }

    // Block sum, then one scaled atomicAdd per block.
    __shared__ float s[TPB];
    s[threadIdx.x] = best;
    __syncthreads();
    #pragma unroll
    for (int stride = TPB / 2; stride > 0; stride >>= 1) {
        if (threadIdx.x < stride) s[threadIdx.x] += s[threadIdx.x + stride];
        __syncthreads();
    }
    if (threadIdx.x == 0)
        atomicAdd(out, s[0] * (0.5f / (float)CN));
}

extern "C" void kernel_launch(void* const* d_in, const int* in_sizes, int n_in,
                              void* d_out, int out_size) {
    const float* x = (const float*)d_in[0];   // inputs  [16384] f32
    const float* y = (const float*)d_in[1];   // targets [16384] f32
    float* out = (float*)d_out;

    build_kernel<<<1, 1024>>>(x, y, out);
    search_kernel<<<2 * CN / TPB, TPB>>>(x, y, out);
}

// round 5
// speedup vs baseline: 1.6132x; 1.6132x over previous
#include <cuda_runtime.h>
#include <math_constants.h>

// Chamfer 1D, single persistent kernel with device-side grid barriers.
// N = M = 16384 fp32. out = 0.5*(sum_i min_j|x_i-y_j| + sum_j min_i|y_j-x_i|)/N

#define CN    16384
#define NB    4096
#define NBLK  32
#define TPB   1024
#define NPH   3u                  // barriers per launch
#define BLO   (-8.0f)
#define BW    (16.0f / (float)NB)
#define BINVW ((float)NB / 16.0f)

// All zero-initialized at module load; every field is either monotonic (g_bar),
// re-zeroed inside the launch before reuse (g_hist, out), or fully overwritten
// every launch (g_off, g_cur, g_sorted, g_bkt) -> graph-replay safe.
__device__ unsigned g_bar;
__device__ unsigned g_hist[2][NB];
__device__ unsigned g_off[2][NB + 1];
__device__ unsigned g_cur[2][NB];
__device__ float    g_sorted[2][CN];
__device__ int      g_bkt[2][CN];

__device__ __forceinline__ int bucket_of(float v) {
    int b = (int)((v - BLO) * BINVW);
    return min(NB - 1, max(0, b));
}

// Grid barrier: monotonic arrival counter, target passed in. Release via
// __threadfence before arrive; acquire via fence after the spin.
__device__ __forceinline__ void grid_barrier(unsigned tgt) {
    __syncthreads();
    if (threadIdx.x == 0) {
        __threadfence();
        atomicAdd(&g_bar, 1u);
        while (atomicAdd(&g_bar, 0u) < tgt) __nanosleep(64);
        __threadfence();
    }
    __syncthreads();
}

__global__ void __launch_bounds__(TPB, 1)
chamfer_all(const float* __restrict__ x, const float* __restrict__ y,
            float* __restrict__ out) {
    __shared__ unsigned s_base;
    __shared__ unsigned s_warp[32];
    __shared__ float    s_red[TPB];

    const int t  = threadIdx.x;
    const int gi = blockIdx.x * TPB + t;     // 0 .. 32767
    const int a  = gi >= CN;                 // which array this thread owns
    const int i  = gi - a * CN;
    const unsigned lane = t & 31, wid = t >> 5;

    // Recover this launch's barrier base from the monotonic counter.
    // At read time counter is in [L*NPH*NBLK, L*NPH*NBLK + NBLK - 1]
    // (no block can pass barrier 1 until all blocks have read), so floor-div
    // is exact.
    if (t == 0)
        s_base = (atomicAdd(&g_bar, 0u) / (NPH * NBLK)) * (NPH * NBLK);
    __syncthreads();
    const unsigned base = s_base;

    // ── Phase 0: histogram (g_hist pre-zeroed), zero output accumulator ──
    const float q = a ? y[i] : x[i];
    const int   b = bucket_of(q);
    atomicAdd(&g_hist[a][b], 1u);
    if (gi == 0) out[0] = 0.0f;
    grid_barrier(base + NBLK);

    // ── Phase 1: block 0 exclusive-scans both histograms ──
    if (blockIdx.x == 0) {
        #pragma unroll
        for (int arr = 0; arr < 2; arr++) {
            unsigned v0 = g_hist[arr][4 * t + 0];
            unsigned v1 = g_hist[arr][4 * t + 1];
            unsigned v2 = g_hist[arr][4 * t + 2];
            unsigned v3 = g_hist[arr][4 * t + 3];
            unsigned csum = v0 + v1 + v2 + v3;
            // two-level inclusive scan of per-thread chunk sums
            unsigned sc = csum;
            #pragma unroll
            for (int d = 1; d < 32; d <<= 1) {
                unsigned n = __shfl_up_sync(0xFFFFFFFFu, sc, d);
                if (lane >= d) sc += n;
            }
            if (lane == 31) s_warp[wid] = sc;
            __syncthreads();
            if (wid == 0) {
                unsigned w = s_warp[lane];
                #pragma unroll
                for (int d = 1; d < 32; d <<= 1) {
                    unsigned n = __shfl_up_sync(0xFFFFFFFFu, w, d);
                    if (lane >= d) w += n;
                }
                s_warp[lane] = w;
            }
            __syncthreads();
            unsigned ex = (wid ? s_warp[wid - 1] : 0u) + sc - csum;
            unsigned o0 = ex, o1 = o0 + v0, o2 = o1 + v1, o3 = o2 + v2;
            g_off[arr][4 * t + 0] = o0;  g_cur[arr][4 * t + 0] = o0;
            g_off[arr][4 * t + 1] = o1;  g_cur[arr][4 * t + 1] = o1;
            g_off[arr][4 * t + 2] = o2;  g_cur[arr][4 * t + 2] = o2;
            g_off[arr][4 * t + 3] = o3;  g_cur[arr][4 * t + 3] = o3;
            if (t == 0) g_off[arr][NB] = CN;
            __syncthreads();
        }
    }
    grid_barrier(base + 2 * NBLK);

    // ── Phase 2: counting-sort scatter (+ bucket id), re-zero hist ──
    {
        unsigned p = atomicAdd(&g_cur[a][b], 1u);
        g_sorted[a][p] = q;
        g_bkt[a][p]    = b;
    }
    if (gi < 2 * NB) ((unsigned*)g_hist)[gi] = 0u;   // ready for next replay
    grid_barrier(base + 3 * NBLK);

    // ── Phase 3: nearest-neighbor search with O(1) nonempty-bucket hops ──
    const float*    __restrict__ cArr = g_sorted[1 - a];
    const unsigned* __restrict__ off  = g_off[1 - a];
    const int*      __restrict__ bkt  = g_bkt[1 - a];

    float best = CUDART_INF_F;
    const unsigned e0 = off[b], e1 = off[b + 1];
    for (unsigned k = e0; k < e1; k++)
        best = fminf(best, fabsf(q - cArr[k]));

    // Left chain: element e-1 lives in the nearest nonempty bucket < current.
    unsigned e = e0;
    while (e > 0) {
        int bl = bkt[e - 1];
        float gap = q - (BLO + (float)(bl + 1) * BW);  // <= true dist to bucket bl
        if (gap >= best) break;
        unsigned s = off[bl];
        for (unsigned k = s; k < e; k++)
            best = fminf(best, fabsf(q - cArr[k]));
        e = s;
    }
    // Right chain: element e lives in the nearest nonempty bucket > current.
    e = e1;
    while (e < CN) {
        int br = bkt[e];
        float gap = (BLO + (float)br * BW) - q;
        if (gap >= best) break;
        unsigned s = off[br + 1];
        for (unsigned k = e; k < s; k++)
            best = fminf(best, fabsf(q - cArr[k]));
        e = s;
    }

    // Block reduction, one atomicAdd per block.
    s_red[t] = best;
    __syncthreads();
    #pragma unroll
    for (int stride = TPB / 2; stride > 0; stride >>= 1) {
        if (t < stride) s_red[t] += s_red[t + stride];
        __syncthreads();
    }
    if (t == 0)
        atomicAdd(out, s_red[0] * (0.5f / (float)CN));
}

extern "C" void kernel_launch(void* const* d_in, const int* in_sizes, int n_in,
                              void* d_out, int out_size) {
    const float* x = (const float*)d_in[0];   // inputs  [16384] f32
    const float* y = (const float*)d_in[1];   // targets [16384] f32
    float* out = (float*)d_out;

    chamfer_all<<<NBLK, TPB>>>(x, y, out);
}

// round 6
// speedup vs baseline: 1.9106x; 1.1844x over previous
#include <cuda_runtime.h>
#include <math_constants.h>

// Chamfer 1D, single persistent kernel. N = M = 16384 fp32.
// out = 0.5*(sum_i min_j|x_i-y_j| + sum_j min_i|y_j-x_i|)/N
//
// Pipeline (3 grid barriers):
//   ph0: global histogram; atomicAdd return value = within-bucket rank.
//   ph1: EVERY block redundantly scans both histograms into its own smem
//        (kills block-0 serialization; search reads offsets via LDS).
//   ph2: scatter to g_sorted/g_bkt at off[b]+rank (no cursor atomics);
//        re-zero g_hist for the next graph replay.
//   ph3: ring search with O(1) nonempty-bucket hops; block sum; atomicAdd.

#define CN    16384
#define NB    4096
#define NBLK  32
#define TPB   1024
#define NPH   3u
#define BLO   (-8.0f)
#define BW    (16.0f / (float)NB)
#define BINVW ((float)NB / 16.0f)

// Zero-initialized at load. g_bar monotonic; g_hist re-zeroed in-launch;
// g_sorted/g_bkt fully overwritten each launch -> graph-replay safe.
__device__ unsigned g_bar;
__device__ unsigned g_hist[2][NB];
__device__ float    g_sorted[2][CN];
__device__ int      g_bkt[2][CN];

__device__ __forceinline__ int bucket_of(float v) {
    int b = (int)((v - BLO) * BINVW);
    return min(NB - 1, max(0, b));
}

__device__ __forceinline__ void grid_barrier(unsigned tgt) {
    __syncthreads();
    if (threadIdx.x == 0) {
        __threadfence();
        atomicAdd(&g_bar, 1u);
        while (atomicAdd(&g_bar, 0u) < tgt) __nanosleep(32);
        __threadfence();
    }
    __syncthreads();
}

__global__ void __launch_bounds__(TPB, 1)
chamfer_all(const float* __restrict__ x, const float* __restrict__ y,
            float* __restrict__ out) {
    __shared__ unsigned s_off[2][NB + 1];   // per-block copy of both offset tables
    __shared__ unsigned s_warp[32];
    __shared__ unsigned s_base;
    __shared__ float    s_red[32];

    const int t  = threadIdx.x;
    const int gi = blockIdx.x * TPB + t;     // 0 .. 32767
    const int a  = gi >= CN;                 // owning array
    const int i  = gi - a * CN;
    const unsigned lane = t & 31, wid = t >> 5;

    // Recover this launch's barrier base from the monotonic counter.
    if (t == 0)
        s_base = (atomicAdd(&g_bar, 0u) / (NPH * NBLK)) * (NPH * NBLK);
    __syncthreads();
    const unsigned base = s_base;

    // ── ph0: histogram; returned old count = within-bucket rank ──
    const float q = a ? y[i] : x[i];
    const int   b = bucket_of(q);
    const unsigned rank = atomicAdd(&g_hist[a][b], 1u);
    if (gi == 0) out[0] = 0.0f;
    grid_barrier(base + NBLK);

    // ── ph1: every block scans both histograms into smem ──
    #pragma unroll
    for (int arr = 0; arr < 2; arr++) {
        const uint4 v = reinterpret_cast<const uint4*>(g_hist[arr])[t];
        unsigned csum = v.x + v.y + v.z + v.w;
        unsigned sc = csum;
        #pragma unroll
        for (int d = 1; d < 32; d <<= 1) {
            unsigned n = __shfl_up_sync(0xFFFFFFFFu, sc, d);
            if (lane >= (unsigned)d) sc += n;
        }
        if (lane == 31) s_warp[wid] = sc;
        __syncthreads();
        if (wid == 0) {
            unsigned w = s_warp[lane];
            #pragma unroll
            for (int d = 1; d < 32; d <<= 1) {
                unsigned n = __shfl_up_sync(0xFFFFFFFFu, w, d);
                if (lane >= (unsigned)d) w += n;
            }
            s_warp[lane] = w;
        }
        __syncthreads();
        unsigned ex = (wid ? s_warp[wid - 1] : 0u) + sc - csum;
        s_off[arr][4 * t + 0] = ex;
        s_off[arr][4 * t + 1] = ex + v.x;
        s_off[arr][4 * t + 2] = ex + v.x + v.y;
        s_off[arr][4 * t + 3] = ex + v.x + v.y + v.z;
        if (t == 0) s_off[arr][NB] = CN;
        __syncthreads();
    }
    grid_barrier(base + 2 * NBLK);

    // ── ph2: scatter at off[b]+rank (no atomics); re-zero hist for replay ──
    {
        unsigned p = s_off[a][b] + rank;
        g_sorted[a][p] = q;
        g_bkt[a][p]    = b;
    }
    if (gi < 2 * NB) ((unsigned*)g_hist)[gi] = 0u;
    grid_barrier(base + 3 * NBLK);

    // ── ph3: NN ring search; offsets via LDS, elements via L2 ──
    const float* __restrict__ cArr = g_sorted[1 - a];
    const int*   __restrict__ bkt  = g_bkt[1 - a];
    const unsigned* off = s_off[1 - a];

    float best = CUDART_INF_F;
    const unsigned e0 = off[b], e1 = off[b + 1];
    for (unsigned k = e0; k < e1; k++)
        best = fminf(best, fabsf(q - cArr[k]));

    // Left chain: element e-1 lies in the nearest nonempty bucket below.
    unsigned e = e0;
    while (e > 0) {
        int bl = bkt[e - 1];
        float gap = q - (BLO + (float)(bl + 1) * BW);
        if (gap >= best) break;
        unsigned s = off[bl];
        for (unsigned k = s; k < e; k++)
            best = fminf(best, fabsf(q - cArr[k]));
        e = s;
    }
    // Right chain: element e lies in the nearest nonempty bucket above.
    e = e1;
    while (e < CN) {
        int br = bkt[e];
        float gap = (BLO + (float)br * BW) - q;
        if (gap >= best) break;
        unsigned s = off[br + 1];
        for (unsigned k = e; k < s; k++)
            best = fminf(best, fabsf(q - cArr[k]));
        e = s;
    }

    // Block reduction (shuffle + smem), one atomicAdd per block.
    float v = best;
    #pragma unroll
    for (int d = 16; d > 0; d >>= 1)
        v += __shfl_down_sync(0xFFFFFFFFu, v, d);
    if (lane == 0) s_red[wid] = v;
    __syncthreads();
    if (wid == 0) {
        float w = s_red[lane];
        #pragma unroll
        for (int d = 16; d > 0; d >>= 1)
            w += __shfl_down_sync(0xFFFFFFFFu, w, d);
        if (lane == 0)
            atomicAdd(out, w * (0.5f / (float)CN));
    }
}

extern "C" void kernel_launch(void* const* d_in, const int* in_sizes, int n_in,
                              void* d_out, int out_size) {
    const float* x = (const float*)d_in[0];   // inputs  [16384] f32
    const float* y = (const float*)d_in[1];   // targets [16384] f32
    float* out = (float*)d_out;

    chamfer_all<<<NBLK, TPB>>>(x, y, out);
}